// round 5
// baseline (speedup 1.0000x reference)
#include <cuda_runtime.h>

// DepthLoss3D, single fused kernel, single graph node.
// Per channel c, points grouped by grid coordinate (16 groups x 256).
// ds = a*k - b*k, k = spacing[c]*2 > 0. Pairs a<b contribute 0.
// Diagonal (a==b): 0.5*sum|vi-vj| = sum_r v_(r)*(2r-255) over sorted values.
// Pair (a>b), x = p - pb:
//   f(x) = max(x-ds, 0.2ds-x, 0) - 0.2ds*[x<0]
//   sum over sorted B via prefix sums + 3 binary searches.
// Final reduction: per-block partials in device scratch; last block
// (atomicInc wrap -> counter self-resets, replay-safe) sums and writes out.

#define N_ELEM  4096
#define NTASKS  408   // 48 diagonal + 360 pairs

__device__ float        g_scratch[NTASKS];
__device__ unsigned int g_count = 0;

__device__ __forceinline__ int elem_index(int c, int g, int m) {
    if (c == 0)      return (g << 8) + m;
    else if (c == 1) return ((m >> 4) << 8) + (g << 4) + (m & 15);
    else             return (m << 4) + g;
}

__global__ void __launch_bounds__(256) depthloss_fused(
    const float* __restrict__ pred,   // [4096,3]
    const float* __restrict__ spac,   // [3]
    float* __restrict__ out)          // [3]
{
    __shared__ float sv[256];
    __shared__ float sp[257];
    __shared__ float red[8];
    __shared__ int   s_last;

    const int t    = threadIdx.x;
    const int lane = t & 31;
    const int wid  = t >> 5;
    const int bx   = blockIdx.x;

    // Task decode: bx < 48 -> diagonal (c,g); else pair (c, a>b).
    int c, a, b;
    bool diag;
    if (bx < 48) {
        diag = true;
        c = bx >> 4;
        a = b = bx & 15;
    } else {
        diag = false;
        const int idx = bx - 48;
        c = idx / 120;
        const int pq = idx - c * 120;
        a = 1;
        while ((a + 1) * a / 2 <= pq) ++a;
        b = pq - a * (a - 1) / 2;
    }

    float v = pred[elem_index(c, b, t) * 3 + c];
    float p = diag ? 0.0f : pred[elem_index(c, a, t) * 3 + c];

    // ---- Bitonic sort of v across the block (ascending by rank t). ----
#pragma unroll
    for (int k = 2; k <= 256; k <<= 1) {
        const bool up = ((t & k) == 0);
        int j = k >> 1;
        if (j >= 32) {
            // In-place shared phase: one store barrier + one per stage.
            sv[t] = v;
            __syncthreads();
            for (; j >= 32; j >>= 1) {
                if ((t & j) == 0) {
                    const float lo = sv[t], hi = sv[t | j];
                    if ((lo > hi) == up) { sv[t] = hi; sv[t | j] = lo; }
                }
                __syncthreads();
            }
            v = sv[t];
        }
#pragma unroll
        for (; j >= 1; j >>= 1) {
            const float other = __shfl_xor_sync(0xffffffffu, v, j);
            const bool keepMin = (((t & j) == 0) == up);
            v = keepMin ? fminf(v, other) : fmaxf(v, other);
        }
    }

    float partial;
    if (diag) {
        partial = v * (float)(2 * t - 255);
    } else {
        // Inclusive prefix scan of sorted v.
        float x = v;
#pragma unroll
        for (int off = 1; off < 32; off <<= 1) {
            const float y = __shfl_up_sync(0xffffffffu, x, off);
            if (lane >= off) x += y;
        }
        __syncthreads();
        if (lane == 31) red[wid] = x;
        __syncthreads();
        float woff = 0.0f;
#pragma unroll
        for (int w = 0; w < 8; ++w)
            woff += (w < wid) ? red[w] : 0.0f;

        sv[t]     = v;
        sp[t + 1] = x + woff;
        if (t == 0) sp[0] = 0.0f;
        __syncthreads();

        const float k  = spac[c] * 2.0f;
        const float ds = (float)a * k - (float)b * k;  // reference rounding order
        const float c1 = 0.2f * ds;
        const float k1 = p - ds;
        const float k2 = p - c1;

        int cnt1 = 0, cnt2 = 0, cnt3 = 0;
#pragma unroll
        for (int s = 128; s > 0; s >>= 1) {
            cnt1 += (sv[cnt1 + s - 1] <  k1) ? s : 0;
            cnt2 += (sv[cnt2 + s - 1] <= k2) ? s : 0;
            cnt3 += (sv[cnt3 + s - 1] <= p ) ? s : 0;
        }
        cnt1 += (sv[cnt1] <  k1) ? 1 : 0;
        cnt2 += (sv[cnt2] <= k2) ? 1 : 0;
        cnt3 += (sv[cnt3] <= p ) ? 1 : 0;

        const float T = sp[256];
        partial = (float)cnt1 * k1 - sp[cnt1]
                + (T - sp[cnt2]) - (float)(256 - cnt2) * k2
                - c1 * (float)(256 - cnt3);
    }

    // ---- Block reduction of partial. ----
#pragma unroll
    for (int off = 16; off > 0; off >>= 1)
        partial += __shfl_xor_sync(0xffffffffu, partial, off);
    __syncthreads();
    if (lane == 0) red[wid] = partial;
    __syncthreads();

    // ---- Publish partial; last block reduces all and writes out. ----
    if (t == 0) {
        const float tot = red[0] + red[1] + red[2] + red[3]
                        + red[4] + red[5] + red[6] + red[7];
        g_scratch[bx] = tot;
        __threadfence();
        const unsigned int prev = atomicInc(&g_count, NTASKS - 1);  // wraps to 0
        s_last = (prev == NTASKS - 1);
    }
    __syncthreads();

    if (s_last) {
        __shared__ float chs[3];
        if (t < 3) chs[t] = 0.0f;
        __syncthreads();
        for (int idx = t; idx < NTASKS; idx += 256) {
            const int cc = (idx < 48) ? (idx >> 4) : (idx - 48) / 120;
            atomicAdd(&chs[cc], g_scratch[idx]);
        }
        __syncthreads();
        if (t < 3)
            out[t] = chs[t] * (1.0f / ((float)N_ELEM * (float)N_ELEM));
    }
}

extern "C" void kernel_launch(void* const* d_in, const int* in_sizes, int n_in,
                              void* d_out, int out_size)
{
    (void)in_sizes; (void)n_in; (void)out_size;
    const float* pred = (const float*)d_in[0];
    const float* spac = (const float*)d_in[1];
    float* out = (float*)d_out;

    depthloss_fused<<<NTASKS, 256>>>(pred, spac, out);
}

// round 6
// speedup vs baseline: 1.6500x; 1.6500x over previous
#include <cuda_runtime.h>

// DepthLoss3D, single fused kernel (+ memset node), static bitonic sort.
// Per channel c, points grouped by grid coordinate (16 groups x 256).
// ds = a*k - b*k, k = spacing[c]*2 > 0. Pairs a<b contribute 0.
// Diagonal (a==b): 0.5*sum|vi-vj| = sum_r v_(r)*(2r-255) over sorted values.
// Pair (a>b), x = p - pb:
//   f(x) = max(x-ds, 0.2ds-x, 0) - 0.2ds*[x<0]
//   sum over sorted B via prefix sums + 3 binary searches:
//   n1*k1 - P[n1] + (T - P[n2]) - (256-n2)*k2 - 0.2ds*(256-n3)

#define N_ELEM 4096

__device__ __forceinline__ int elem_index(int c, int g, int m) {
    if (c == 0)      return (g << 8) + m;
    else if (c == 1) return ((m >> 4) << 8) + (g << 4) + (m & 15);
    else             return (m << 4) + g;
}

__global__ void __launch_bounds__(256) depthloss_fused(
    const float* __restrict__ pred,   // [4096,3]
    const float* __restrict__ spac,   // [3]
    float* __restrict__ out)          // [3]
{
    __shared__ float sv[256];
    __shared__ float sp[257];
    __shared__ float red[8];

    const int t    = threadIdx.x;
    const int lane = t & 31;
    const int wid  = t >> 5;
    const int bx   = blockIdx.x;

    // Task decode: bx < 48 -> diagonal (c,g); else pair (c, a>b).
    int c, a, b;
    bool diag;
    if (bx < 48) {
        diag = true;
        c = bx >> 4;
        a = b = bx & 15;
    } else {
        diag = false;
        const int idx = bx - 48;
        c = idx / 120;
        const int pq = idx - c * 120;
        a = 1;
        while ((a + 1) * a / 2 <= pq) ++a;
        b = pq - a * (a - 1) / 2;
    }

    float v = pred[elem_index(c, b, t) * 3 + c];
    float p = diag ? 0.0f : pred[elem_index(c, a, t) * 3 + c];

    // ---- Static bitonic sort network (ascending by rank t). ----
    const bool u2   = !(t & 2);
    const bool u4   = !(t & 4);
    const bool u8   = !(t & 8);
    const bool u16  = !(t & 16);
    const bool u32  = !(t & 32);
    const bool u64  = !(t & 64);
    const bool u128 = !(t & 128);

#define SH(J, UP) do {                                              \
        const float o_ = __shfl_xor_sync(0xffffffffu, v, (J));      \
        const bool mn_ = (((t & (J)) == 0) == (UP));                \
        v = mn_ ? fminf(v, o_) : fmaxf(v, o_);                      \
    } while (0)

#define SM(J, UP) do {                                              \
        sv[t] = v;                                                  \
        __syncthreads();                                            \
        const float o_ = sv[t ^ (J)];                               \
        const bool mn_ = (((t & (J)) == 0) == (UP));                \
        v = mn_ ? fminf(v, o_) : fmaxf(v, o_);                      \
        __syncthreads();                                            \
    } while (0)

    SH(1, u2);
    SH(2, u4);  SH(1, u4);
    SH(4, u8);  SH(2, u8);  SH(1, u8);
    SH(8, u16); SH(4, u16); SH(2, u16); SH(1, u16);
    SH(16, u32); SH(8, u32); SH(4, u32); SH(2, u32); SH(1, u32);
    SM(32, u64); SH(16, u64); SH(8, u64); SH(4, u64); SH(2, u64); SH(1, u64);
    SM(64, u128); SM(32, u128); SH(16, u128); SH(8, u128); SH(4, u128);
    SH(2, u128); SH(1, u128);
    SM(128, true); SM(64, true); SM(32, true); SH(16, true); SH(8, true);
    SH(4, true); SH(2, true); SH(1, true);

#undef SH
#undef SM

    const float inv = 1.0f / ((float)N_ELEM * (float)N_ELEM);

    if (diag) {
        float w = v * (float)(2 * t - 255);
#pragma unroll
        for (int off = 16; off > 0; off >>= 1)
            w += __shfl_xor_sync(0xffffffffu, w, off);
        if (lane == 0) red[wid] = w;
        __syncthreads();
        if (t == 0) {
            float tot = red[0] + red[1] + red[2] + red[3]
                      + red[4] + red[5] + red[6] + red[7];
            atomicAdd(&out[c], tot * inv);
        }
        return;
    }

    // ---- Inclusive prefix scan of sorted v. ----
    float x = v;
#pragma unroll
    for (int off = 1; off < 32; off <<= 1) {
        const float y = __shfl_up_sync(0xffffffffu, x, off);
        if (lane >= off) x += y;
    }
    if (lane == 31) red[wid] = x;
    __syncthreads();
    float woff = 0.0f;
#pragma unroll
    for (int w = 0; w < 8; ++w)
        woff += (w < wid) ? red[w] : 0.0f;

    sv[t]     = v;
    sp[t + 1] = x + woff;
    if (t == 0) sp[0] = 0.0f;
    __syncthreads();

    // ---- Closed form. ----
    const float k  = spac[c] * 2.0f;
    const float ds = (float)a * k - (float)b * k;   // reference rounding order
    const float c1 = 0.2f * ds;
    const float k1 = p - ds;
    const float k2 = p - c1;

    int cnt1 = 0, cnt2 = 0, cnt3 = 0;
#pragma unroll
    for (int s = 128; s > 0; s >>= 1) {
        cnt1 += (sv[cnt1 + s - 1] <  k1) ? s : 0;
        cnt2 += (sv[cnt2 + s - 1] <= k2) ? s : 0;
        cnt3 += (sv[cnt3 + s - 1] <= p ) ? s : 0;
    }
    cnt1 += (sv[cnt1] <  k1) ? 1 : 0;
    cnt2 += (sv[cnt2] <= k2) ? 1 : 0;
    cnt3 += (sv[cnt3] <= p ) ? 1 : 0;

    const float T = sp[256];
    float contrib = (float)cnt1 * k1 - sp[cnt1]
                  + (T - sp[cnt2]) - (float)(256 - cnt2) * k2
                  - c1 * (float)(256 - cnt3);

#pragma unroll
    for (int off = 16; off > 0; off >>= 1)
        contrib += __shfl_xor_sync(0xffffffffu, contrib, off);
    __syncthreads();
    if (lane == 0) red[wid] = contrib;
    __syncthreads();
    if (t == 0) {
        float tot = red[0] + red[1] + red[2] + red[3]
                  + red[4] + red[5] + red[6] + red[7];
        atomicAdd(&out[c], tot * inv);
    }
}

extern "C" void kernel_launch(void* const* d_in, const int* in_sizes, int n_in,
                              void* d_out, int out_size)
{
    (void)in_sizes; (void)n_in; (void)out_size;
    const float* pred = (const float*)d_in[0];
    const float* spac = (const float*)d_in[1];
    float* out = (float*)d_out;

    cudaMemsetAsync(out, 0, 3 * sizeof(float));
    depthloss_fused<<<408, 256>>>(pred, spac, out);
}